// round 4
// baseline (speedup 1.0000x reference)
#include <cuda_runtime.h>
#include <cuda_bf16.h>
#include <math.h>
#include <stdint.h>

// ---------------- scratch layout (single __device__ arena, no allocs) ----------------
constexpr size_t OFF_T1     = 0;                       // 64*4096
constexpr size_t OFF_HID    = OFF_T1     + 262144;     // 64*1024
constexpr size_t OFF_T2     = OFF_HID    + 65536;      // 64*4096
constexpr size_t OFF_AUTO   = OFF_T2     + 262144;     // 64*12288
constexpr size_t OFF_NEWX   = OFF_AUTO   + 786432;     // 128*24*512
constexpr size_t OFF_M1     = OFF_NEWX   + 1572864;    // 3072*512
constexpr size_t OFF_H1     = OFF_M1     + 1572864;    // 3072*512
constexpr size_t OFF_M2     = OFF_H1     + 1572864;    // 3072*512
constexpr size_t OFF_OUT1   = OFF_M2     + 1572864;    // 3072*256
constexpr size_t OFF_LSTMIN = OFF_OUT1   + 786432;     // 64*24*512
constexpr size_t OFF_XG     = OFF_LSTMIN + 786432;     // 1536*2048
constexpr size_t OFF_HSEQ0  = OFF_XG     + 3145728;    // 64*24*512
constexpr size_t OFF_HSEQ1  = OFF_HSEQ0  + 786432;     // 64*24*512
constexpr size_t OFF_HA     = OFF_HSEQ1  + 786432;     // 64*512
constexpr size_t OFF_HB     = OFF_HA     + 32768;      // 64*512
constexpr size_t OFF_NF     = OFF_HB     + 32768;      // 64*2560
constexpr size_t OFF_B0     = OFF_NF     + 163840;     // 2048
constexpr size_t OFF_B1     = OFF_B0     + 2048;       // 2048
constexpr size_t OFF_W0HI   = OFF_B1     + 2048;       // 2048*512 bf16 = 524288 floats
constexpr size_t OFF_W0LO   = OFF_W0HI   + 524288;
constexpr size_t OFF_W1HI   = OFF_W0LO   + 524288;
constexpr size_t OFF_W1LO   = OFF_W1HI   + 524288;
constexpr size_t OFF_GP     = OFF_W1LO   + 524288;     // split-K partials (up to 16 x 262144)
constexpr size_t TOTAL_SCRATCH = OFF_GP  + 4194304;

__device__ float g_scratch[TOTAL_SCRATCH];

// grid-barrier state (monotonic generation; safe across graph replays)
__device__ unsigned g_bar_cnt = 0;
__device__ unsigned g_bar_gen = 0;

__device__ __forceinline__ float sigmoidf_(float v) { return 1.0f / (1.0f + expf(-v)); }

// ---------------- bf16x3 tensor-core GEMM primitives ----------------
__device__ __forceinline__ void bsplit(float x, __nv_bfloat16& h, __nv_bfloat16& l) {
    h = __float2bfloat16(x);
    l = __float2bfloat16(x - __bfloat162float(h));
}
__device__ __forceinline__ uint32_t smem_u32(const void* p) {
    return (uint32_t)__cvta_generic_to_shared(p);
}
__device__ __forceinline__ void ldm_x4(uint32_t addr, uint32_t r[4]) {
    asm volatile("ldmatrix.sync.aligned.m8n8.x4.shared.b16 {%0,%1,%2,%3}, [%4];"
                 : "=r"(r[0]), "=r"(r[1]), "=r"(r[2]), "=r"(r[3]) : "r"(addr));
}
__device__ __forceinline__ void ldm_x2(uint32_t addr, uint32_t r[2]) {
    asm volatile("ldmatrix.sync.aligned.m8n8.x2.shared.b16 {%0,%1}, [%2];"
                 : "=r"(r[0]), "=r"(r[1]) : "r"(addr));
}
__device__ __forceinline__ void mma16816(float d[4], const uint32_t a[4], const uint32_t b[2]) {
    asm volatile("mma.sync.aligned.m16n8k16.row.col.f32.bf16.bf16.f32 "
                 "{%0,%1,%2,%3}, {%4,%5,%6,%7}, {%8,%9}, {%0,%1,%2,%3};"
                 : "+f"(d[0]), "+f"(d[1]), "+f"(d[2]), "+f"(d[3])
                 : "r"(a[0]), "r"(a[1]), "r"(a[2]), "r"(a[3]), "r"(b[0]), "r"(b[1]));
}

constexpr int PAD = 40;  // bf16 row stride: 80 bytes (conflict-free ldmatrix)

// ---------------- generic batched GEMM (unchanged from R2, proven) ----------------
__global__ __launch_bounds__(256) void gemm_bf3(
    const float* __restrict__ A, const float* __restrict__ W,
    const float* __restrict__ bias, float* __restrict__ C,
    int M, int N, int K, int kchunks, int relu)
{
    __shared__ __nv_bfloat16 sAh[64 * PAD], sAl[64 * PAD];
    __shared__ __nv_bfloat16 sWh[128 * PAD], sWl[128 * PAD];

    const int bm = blockIdx.y * 64;
    const int bn = blockIdx.x * 128;
    const int z  = blockIdx.z;
    const int Kc = K / kchunks;
    const int tid  = threadIdx.x;
    const int lane = tid & 31, warp = tid >> 5;
    const int wm = (warp & 1) * 32;
    const int wn = (warp >> 1) * 32;

    float acc[2][4][4];
#pragma unroll
    for (int mi = 0; mi < 2; mi++)
#pragma unroll
        for (int ni = 0; ni < 4; ni++)
#pragma unroll
            for (int e = 0; e < 4; e++) acc[mi][ni][e] = 0.0f;

    const float* Ab = A + (size_t)bm * K + (size_t)z * Kc;
    const float* Wb = W + (size_t)bn * K + (size_t)z * Kc;

    const int arow = lane & 15, acol8 = (lane >> 4) * 8;
    const int brow = lane & 7,  bcol8 = ((lane >> 3) & 1) * 8;

    for (int kt = 0; kt < Kc; kt += 32) {
#pragma unroll
        for (int i = 0; i < 2; i++) {
            int f = tid + i * 256;
            int r = f >> 3, c = (f & 7) * 4;
            float4 v = *(const float4*)(Ab + (size_t)r * K + kt + c);
            bsplit(v.x, sAh[r * PAD + c + 0], sAl[r * PAD + c + 0]);
            bsplit(v.y, sAh[r * PAD + c + 1], sAl[r * PAD + c + 1]);
            bsplit(v.z, sAh[r * PAD + c + 2], sAl[r * PAD + c + 2]);
            bsplit(v.w, sAh[r * PAD + c + 3], sAl[r * PAD + c + 3]);
        }
#pragma unroll
        for (int i = 0; i < 4; i++) {
            int f = tid + i * 256;
            int r = f >> 3, c = (f & 7) * 4;
            float4 v = *(const float4*)(Wb + (size_t)r * K + kt + c);
            bsplit(v.x, sWh[r * PAD + c + 0], sWl[r * PAD + c + 0]);
            bsplit(v.y, sWh[r * PAD + c + 1], sWl[r * PAD + c + 1]);
            bsplit(v.z, sWh[r * PAD + c + 2], sWl[r * PAD + c + 2]);
            bsplit(v.w, sWh[r * PAD + c + 3], sWl[r * PAD + c + 3]);
        }
        __syncthreads();

#pragma unroll
        for (int ks = 0; ks < 32; ks += 16) {
            uint32_t ah[2][4], al[2][4], bh[4][2], bl[4][2];
#pragma unroll
            for (int mi = 0; mi < 2; mi++) {
                int r = wm + mi * 16 + arow, c = ks + acol8;
                ldm_x4(smem_u32(&sAh[r * PAD + c]), ah[mi]);
                ldm_x4(smem_u32(&sAl[r * PAD + c]), al[mi]);
            }
#pragma unroll
            for (int ni = 0; ni < 4; ni++) {
                int r = wn + ni * 8 + brow, c = ks + bcol8;
                ldm_x2(smem_u32(&sWh[r * PAD + c]), bh[ni]);
                ldm_x2(smem_u32(&sWl[r * PAD + c]), bl[ni]);
            }
#pragma unroll
            for (int mi = 0; mi < 2; mi++)
#pragma unroll
                for (int ni = 0; ni < 4; ni++) {
                    mma16816(acc[mi][ni], ah[mi], bh[ni]);
                    mma16816(acc[mi][ni], al[mi], bh[ni]);
                    mma16816(acc[mi][ni], ah[mi], bl[ni]);
                }
        }
        __syncthreads();
    }

    float* Cz = C + (size_t)z * ((size_t)M * N);
    const int mr = lane >> 2;
    const int nc = (lane & 3) * 2;
#pragma unroll
    for (int mi = 0; mi < 2; mi++)
#pragma unroll
        for (int ni = 0; ni < 4; ni++) {
            int m0 = bm + wm + mi * 16 + mr;
            int n0 = bn + wn + ni * 8 + nc;
            float2 v0 = make_float2(acc[mi][ni][0], acc[mi][ni][1]);
            float2 v1 = make_float2(acc[mi][ni][2], acc[mi][ni][3]);
            if (kchunks == 1) {
                if (bias) {
                    float b0v = bias[n0], b1v = bias[n0 + 1];
                    v0.x += b0v; v0.y += b1v; v1.x += b0v; v1.y += b1v;
                }
                if (relu) {
                    v0.x = fmaxf(v0.x, 0.0f); v0.y = fmaxf(v0.y, 0.0f);
                    v1.x = fmaxf(v1.x, 0.0f); v1.y = fmaxf(v1.y, 0.0f);
                }
            }
            *(float2*)(Cz + (size_t)m0 * N + n0) = v0;
            *(float2*)(Cz + (size_t)(m0 + 8) * N + n0) = v1;
        }
}

// ---------------- fused persistent LSTM layer ----------------
// 128 blocks, 256 threads. Block j owns hidden units [j*4, j*4+4) -> 16 gate rows
// {g*512 + j*4 + u}. Whh slice gathered+split to smem ONCE; c state in smem.
// Per step: bf16x3 mma over K=512 against double-buffered global H, gate update
// in-block, grid barrier.
constexpr int LSTM_NBLK = 128;
// dynamic smem offsets (bytes)
constexpr int SM_WHI = 0;                    // 16 iters * 16 rows * 40 * 2B = 20480
constexpr int SM_WLO = 20480;
constexpr int SM_AHI = 40960;                // 64 * 40 * 2B = 5120
constexpr int SM_ALO = 46080;
constexpr int SM_P   = 51200;                // 64*16 fp32 = 4096
constexpr int SM_C   = 55296;                // 256 fp32 = 1024
constexpr int SM_TOTAL_LSTM = 56320;

__device__ __forceinline__ void grid_bar() {
    __syncthreads();
    if (threadIdx.x == 0) {
        __threadfence();
        unsigned gen = *((volatile unsigned*)&g_bar_gen);
        if (atomicAdd(&g_bar_cnt, 1) == LSTM_NBLK - 1) {
            atomicExch(&g_bar_cnt, 0);
            __threadfence();
            atomicExch(&g_bar_gen, gen + 1);
        } else {
            while (*((volatile unsigned*)&g_bar_gen) == gen) __nanosleep(40);
        }
        __threadfence();
    }
    __syncthreads();
}

__global__ __launch_bounds__(256, 1) void fused_lstm(
    const __nv_bfloat16* __restrict__ WHI, const __nv_bfloat16* __restrict__ WLO,
    const float* __restrict__ XG, const float* __restrict__ h0s,
    const float* __restrict__ c0s, float* __restrict__ HSEQ,
    float* __restrict__ HB0, float* __restrict__ HB1)
{
    extern __shared__ char smem[];
    __nv_bfloat16* sWh = (__nv_bfloat16*)(smem + SM_WHI);
    __nv_bfloat16* sWl = (__nv_bfloat16*)(smem + SM_WLO);
    __nv_bfloat16* sAh = (__nv_bfloat16*)(smem + SM_AHI);
    __nv_bfloat16* sAl = (__nv_bfloat16*)(smem + SM_ALO);
    float* P   = (float*)(smem + SM_P);
    float* csh = (float*)(smem + SM_C);

    const int j = blockIdx.x;
    const int tid = threadIdx.x;
    const int lane = tid & 31, warp = tid >> 5;
    const int wm = (warp & 3) * 16;   // 4 warps along M (batches)
    const int wn = (warp >> 2) * 8;   // 2 warps along N (gate cols)

    // gather Whh slice: 16 gate rows x 512 -> chunked smem [it][16][40]
    for (int idx = tid; idx < 16 * 512; idx += 256) {
        int n = idx >> 9, k = idx & 511;
        int grow = (n >> 2) * 512 + j * 4 + (n & 3);
        int so = (k >> 5) * 640 + n * 40 + (k & 31);
        sWh[so] = WHI[(size_t)grow * 512 + k];
        sWl[so] = WLO[(size_t)grow * 512 + k];
    }
    // init c state + H(0)
    {
        int b = tid >> 2, u = tid & 3;
        int col = j * 4 + u;
        csh[tid] = c0s[b * 512 + col];
        HB0[b * 512 + col] = h0s[b * 512 + col];
    }
    __threadfence();
    grid_bar();

    const int arow = lane & 15, acol8 = (lane >> 4) * 8;
    const int brow = lane & 7,  bcol8 = ((lane >> 3) & 1) * 8;

    for (int t = 0; t < 24; t++) {
        const float* Hin = (t & 1) ? HB1 : HB0;
        float* Hout      = (t & 1) ? HB0 : HB1;

        float acc[4] = {0.0f, 0.0f, 0.0f, 0.0f};

        for (int it = 0; it < 16; it++) {
            const int kt = it * 32;
            // stage H chunk 64x32 (L1-bypassing loads: other SMs rewrote it)
#pragma unroll
            for (int i = 0; i < 2; i++) {
                int f = tid + i * 256;
                int r = f >> 3, c = (f & 7) * 4;
                float4 v = __ldcg((const float4*)(Hin + r * 512 + kt + c));
                bsplit(v.x, sAh[r * PAD + c + 0], sAl[r * PAD + c + 0]);
                bsplit(v.y, sAh[r * PAD + c + 1], sAl[r * PAD + c + 1]);
                bsplit(v.z, sAh[r * PAD + c + 2], sAl[r * PAD + c + 2]);
                bsplit(v.w, sAh[r * PAD + c + 3], sAl[r * PAD + c + 3]);
            }
            __syncthreads();

            const __nv_bfloat16* wh = sWh + it * 640;
            const __nv_bfloat16* wl = sWl + it * 640;
#pragma unroll
            for (int ks = 0; ks < 32; ks += 16) {
                uint32_t ah[4], al[4], bh[2], bl[2];
                ldm_x4(smem_u32(&sAh[(wm + arow) * PAD + ks + acol8]), ah);
                ldm_x4(smem_u32(&sAl[(wm + arow) * PAD + ks + acol8]), al);
                ldm_x2(smem_u32(&wh[(wn + brow) * PAD + ks + bcol8]), bh);
                ldm_x2(smem_u32(&wl[(wn + brow) * PAD + ks + bcol8]), bl);
                mma16816(acc, ah, bh);
                mma16816(acc, al, bh);
                mma16816(acc, ah, bl);
            }
            __syncthreads();
        }

        // write pre-activations to smem P [64][16]
        {
            int r0 = wm + (lane >> 2);
            int c0 = wn + (lane & 3) * 2;
            P[r0 * 16 + c0] = acc[0];       P[r0 * 16 + c0 + 1] = acc[1];
            P[(r0 + 8) * 16 + c0] = acc[2]; P[(r0 + 8) * 16 + c0 + 1] = acc[3];
        }
        __syncthreads();

        // gate update: thread -> (batch b, unit u)
        {
            int b = tid >> 2, u = tid & 3;
            int col = j * 4 + u;
            const float* xg = XG + (size_t)(b * 24 + t) * 2048 + col;
            float gi = P[b * 16 + u]      + xg[0];
            float gf = P[b * 16 + 4 + u]  + xg[512];
            float gg = P[b * 16 + 8 + u]  + xg[1024];
            float go = P[b * 16 + 12 + u] + xg[1536];
            float c = sigmoidf_(gf) * csh[tid] + sigmoidf_(gi) * tanhf(gg);
            csh[tid] = c;
            float hn = sigmoidf_(go) * tanhf(c);
            Hout[b * 512 + col] = hn;
            HSEQ[(size_t)(b * 24 + t) * 512 + col] = hn;
        }
        __threadfence();
        grid_bar();
    }
}

// split fp32 weights to bf16 hi/lo
__global__ void split_w(const float* __restrict__ W, __nv_bfloat16* __restrict__ HI,
                        __nv_bfloat16* __restrict__ LO, int n)
{
    int i = blockIdx.x * blockDim.x + threadIdx.x;
    if (i >= n) return;
    __nv_bfloat16 h, l;
    bsplit(W[i], h, l);
    HI[i] = h; LO[i] = l;
}

// sum split-K partials + bias + optional relu
__global__ void reduce_bias_act(const float* __restrict__ GP, const float* __restrict__ bias,
                                float* __restrict__ out, int total, int N, int kchunks, int relu)
{
    int i = blockIdx.x * blockDim.x + threadIdx.x;
    if (i >= total) return;
    float s = 0.0f;
    for (int z = 0; z < kchunks; z++) s += GP[(size_t)z * total + i];
    if (bias) s += bias[i % N];
    if (relu) s = fmaxf(s, 0.0f);
    out[i] = s;
}

__global__ void ae_post(const float* __restrict__ x, const float* __restrict__ AUTO,
                        float* __restrict__ NEWX, float* __restrict__ outAuto)
{
    int i = blockIdx.x * blockDim.x + threadIdx.x;
    if (i >= 786432) return;
    float xv = x[i], av = AUTO[i];
    NEWX[i] = xv;
    NEWX[786432 + i] = xv - av;
    outAuto[i] = av;
}

__global__ void permute_lstm_in(const float* __restrict__ OUT1, float* __restrict__ LSTMIN)
{
    int f = blockIdx.x * blockDim.x + threadIdx.x;
    if (f >= 786432) return;
    int s  = f >> 15;
    int b2 = (f >> 8) & 127;
    int g  = f & 255;
    LSTMIN[f] = OUT1[(size_t)b2 * 6144 + s * 256 + g];
}

__global__ void comb_bias(const float* __restrict__ bih0, const float* __restrict__ bhh0,
                          const float* __restrict__ bih1, const float* __restrict__ bhh1,
                          float* __restrict__ B0, float* __restrict__ B1)
{
    int i = blockIdx.x * blockDim.x + threadIdx.x;
    if (i >= 2048) return;
    B0[i] = bih0[i] + bhh0[i];
    B1[i] = bih1[i] + bhh1[i];
}

__global__ void pred_fc(const float* __restrict__ HSEQ1, const float* __restrict__ lfcW,
                        const float* __restrict__ lfcb, float* __restrict__ NF)
{
    __shared__ float hrow[512];
    int b = blockIdx.x / 12;
    int p = blockIdx.x % 12;
    int row = b * 24 + 12 + p;
    int tid = threadIdx.x;  // 128 threads
    *(float4*)(&hrow[tid * 4]) = *(const float4*)(HSEQ1 + (size_t)row * 512 + tid * 4);
    __syncthreads();
    float acc = lfcb[tid];
    const float* wr = lfcW + (size_t)tid * 512;
#pragma unroll 8
    for (int k = 0; k < 512; k++) acc += hrow[k] * wr[k];
    NF[(size_t)b * 2560 + p * 128 + tid] = acc;
}

__global__ void concat_hidden(const float* __restrict__ HID, float* __restrict__ NF)
{
    int i = blockIdx.x * blockDim.x + threadIdx.x;
    if (i >= 65536) return;
    int b = i >> 10, j = i & 1023;
    NF[(size_t)b * 2560 + 1536 + j] = HID[i];
}

// ---------------- host launch sequence ----------------
extern "C" void kernel_launch(void* const* d_in, const int* in_sizes, int n_in,
                              void* d_out, int out_size)
{
    (void)in_sizes; (void)n_in; (void)out_size;
    const float* x     = (const float*)d_in[0];
    const float* adj   = (const float*)d_in[1];
    const float* h0    = (const float*)d_in[2];
    const float* c0    = (const float*)d_in[3];
    const float* fc11W = (const float*)d_in[4];
    const float* fc11b = (const float*)d_in[5];
    const float* fc12W = (const float*)d_in[6];
    const float* fc12b = (const float*)d_in[7];
    const float* fc21W = (const float*)d_in[8];
    const float* fc21b = (const float*)d_in[9];
    const float* fc22W = (const float*)d_in[10];
    const float* fc22b = (const float*)d_in[11];
    const float* gc1W  = (const float*)d_in[12];
    const float* gc1b  = (const float*)d_in[13];
    const float* gc2W  = (const float*)d_in[14];
    const float* gc2b  = (const float*)d_in[15];
    const float* Wih0  = (const float*)d_in[16];
    const float* Whh0  = (const float*)d_in[17];
    const float* bih0  = (const float*)d_in[18];
    const float* bhh0  = (const float*)d_in[19];
    const float* Wih1  = (const float*)d_in[20];
    const float* Whh1  = (const float*)d_in[21];
    const float* bih1  = (const float*)d_in[22];
    const float* bhh1  = (const float*)d_in[23];
    const float* lfcW  = (const float*)d_in[24];
    const float* lfcb  = (const float*)d_in[25];
    const float* fcW   = (const float*)d_in[26];
    const float* fcb   = (const float*)d_in[27];

    float* out = (float*)d_out;          // [64,12,512]
    float* outAuto = out + 393216;       // [64,24,512]

    float* Sc;
    cudaGetSymbolAddress((void**)&Sc, g_scratch);
    float* T1     = Sc + OFF_T1;
    float* HID    = Sc + OFF_HID;
    float* T2     = Sc + OFF_T2;
    float* AUTO   = Sc + OFF_AUTO;
    float* NEWX   = Sc + OFF_NEWX;
    float* M1     = Sc + OFF_M1;
    float* H1     = Sc + OFF_H1;
    float* M2     = Sc + OFF_M2;
    float* OUT1   = Sc + OFF_OUT1;
    float* LSTMIN = Sc + OFF_LSTMIN;
    float* XG     = Sc + OFF_XG;
    float* HSEQ0  = Sc + OFF_HSEQ0;
    float* HSEQ1  = Sc + OFF_HSEQ1;
    float* HA     = Sc + OFF_HA;
    float* HB     = Sc + OFF_HB;
    float* NF     = Sc + OFF_NF;
    float* B0     = Sc + OFF_B0;
    float* B1     = Sc + OFF_B1;
    float* GP     = Sc + OFF_GP;
    __nv_bfloat16* W0HI = (__nv_bfloat16*)(Sc + OFF_W0HI);
    __nv_bfloat16* W0LO = (__nv_bfloat16*)(Sc + OFF_W0LO);
    __nv_bfloat16* W1HI = (__nv_bfloat16*)(Sc + OFF_W1HI);
    __nv_bfloat16* W1LO = (__nv_bfloat16*)(Sc + OFF_W1LO);

    static bool attr_set = false;
    if (!attr_set) {
        cudaFuncSetAttribute(fused_lstm, cudaFuncAttributeMaxDynamicSharedMemorySize,
                             SM_TOTAL_LSTM);
        attr_set = true;
    }

    // ---- weight prep (independent) ----
    split_w<<<4096, 256>>>(Whh0, W0HI, W0LO, 2048 * 512);
    split_w<<<4096, 256>>>(Whh1, W1HI, W1LO, 2048 * 512);
    comb_bias<<<8, 256>>>(bih0, bhh0, bih1, bhh1, B0, B1);

    // ---- AutoEncoder ----
    gemm_bf3<<<dim3(32, 1, 16), 256>>>(x, fc11W, nullptr, GP, 64, 4096, 12288, 16, 0);
    reduce_bias_act<<<1024, 256>>>(GP, fc11b, T1, 262144, 4096, 16, 1);
    gemm_bf3<<<dim3(8, 1, 16), 256>>>(T1, fc12W, nullptr, GP, 64, 1024, 4096, 16, 0);
    reduce_bias_act<<<256, 256>>>(GP, fc12b, HID, 65536, 1024, 16, 1);
    gemm_bf3<<<dim3(32, 1, 8), 256>>>(HID, fc21W, nullptr, GP, 64, 4096, 1024, 8, 0);
    reduce_bias_act<<<1024, 256>>>(GP, fc21b, T2, 262144, 4096, 8, 1);
    gemm_bf3<<<dim3(96, 1, 4), 256>>>(T2, fc22W, nullptr, GP, 64, 12288, 4096, 4, 0);
    reduce_bias_act<<<3072, 256>>>(GP, fc22b, AUTO, 786432, 12288, 4, 1);
    ae_post<<<3072, 256>>>(x, AUTO, NEWX, outAuto);

    // ---- GCN ----
    gemm_bf3<<<dim3(4, 48, 1), 256>>>(NEWX, adj, nullptr, M1, 3072, 512, 512, 1, 0);
    gemm_bf3<<<dim3(4, 48, 1), 256>>>(M1, gc1W, gc1b, H1, 3072, 512, 512, 1, 1);
    gemm_bf3<<<dim3(4, 48, 1), 256>>>(H1, adj, nullptr, M2, 3072, 512, 512, 1, 0);
    gemm_bf3<<<dim3(2, 48, 1), 256>>>(M2, gc2W, gc2b, OUT1, 3072, 256, 512, 1, 0);
    permute_lstm_in<<<3072, 256>>>(OUT1, LSTMIN);

    // ---- LSTM (fused persistent kernels) ----
    gemm_bf3<<<dim3(16, 24, 1), 256>>>(LSTMIN, Wih0, B0, XG, 1536, 2048, 512, 1, 0);
    fused_lstm<<<LSTM_NBLK, 256, SM_TOTAL_LSTM>>>(W0HI, W0LO, XG, h0, c0, HSEQ0, HA, HB);
    gemm_bf3<<<dim3(16, 24, 1), 256>>>(HSEQ0, Wih1, B1, XG, 1536, 2048, 512, 1, 0);
    fused_lstm<<<LSTM_NBLK, 256, SM_TOTAL_LSTM>>>(W1HI, W1LO, XG, h0 + 32768, c0 + 32768,
                                                  HSEQ1, HA, HB);

    // ---- head ----
    pred_fc<<<768, 128>>>(HSEQ1, lfcW, lfcb, NF);
    concat_hidden<<<256, 256>>>(HID, NF);
    gemm_bf3<<<dim3(48, 1, 4), 256>>>(NF, fcW, nullptr, GP, 64, 6144, 2560, 4, 0);
    reduce_bias_act<<<1536, 256>>>(GP, fcb, out, 393216, 6144, 4, 0);
}

// round 5
// speedup vs baseline: 1.0671x; 1.0671x over previous
#include <cuda_runtime.h>
#include <cuda_bf16.h>
#include <math.h>
#include <stdint.h>

// ---------------- scratch layout (single __device__ arena, no allocs) ----------------
constexpr size_t OFF_T1     = 0;                       // 64*4096
constexpr size_t OFF_HID    = OFF_T1     + 262144;     // 64*1024
constexpr size_t OFF_T2     = OFF_HID    + 65536;      // 64*4096
constexpr size_t OFF_AUTO   = OFF_T2     + 262144;     // 64*12288
constexpr size_t OFF_NEWX   = OFF_AUTO   + 786432;     // 128*24*512
constexpr size_t OFF_M1     = OFF_NEWX   + 1572864;    // 3072*512
constexpr size_t OFF_H1     = OFF_M1     + 1572864;    // 3072*512
constexpr size_t OFF_M2     = OFF_H1     + 1572864;    // 3072*512
constexpr size_t OFF_OUT1   = OFF_M2     + 1572864;    // 3072*256
constexpr size_t OFF_LSTMIN = OFF_OUT1   + 786432;     // 64*24*512
constexpr size_t OFF_XG     = OFF_LSTMIN + 786432;     // 1536*2048
constexpr size_t OFF_HSEQ0  = OFF_XG     + 3145728;    // 64*24*512
constexpr size_t OFF_HSEQ1  = OFF_HSEQ0  + 786432;     // 64*24*512
constexpr size_t OFF_HA     = OFF_HSEQ1  + 786432;     // 64*512
constexpr size_t OFF_HB     = OFF_HA     + 32768;      // 64*512
constexpr size_t OFF_NF     = OFF_HB     + 32768;      // 64*2560
constexpr size_t OFF_B0     = OFF_NF     + 163840;     // 2048
constexpr size_t OFF_B1     = OFF_B0     + 2048;       // 2048
constexpr size_t OFF_W0HI   = OFF_B1     + 2048;       // 2048*512 bf16 = 524288 floats
constexpr size_t OFF_W0LO   = OFF_W0HI   + 524288;
constexpr size_t OFF_W1HI   = OFF_W0LO   + 524288;
constexpr size_t OFF_W1LO   = OFF_W1HI   + 524288;
constexpr size_t OFF_GP     = OFF_W1LO   + 524288;     // split-K partials (up to 16 x 262144)
constexpr size_t TOTAL_SCRATCH = OFF_GP  + 4194304;

__device__ float g_scratch[TOTAL_SCRATCH];

// grid-barrier state (monotonic generation; safe across graph replays)
__device__ unsigned g_bar_cnt = 0;
__device__ unsigned g_bar_gen = 0;

__device__ __forceinline__ float sigmoidf_(float v) { return 1.0f / (1.0f + expf(-v)); }

// ---------------- bf16x3 tensor-core GEMM primitives ----------------
__device__ __forceinline__ void bsplit(float x, __nv_bfloat16& h, __nv_bfloat16& l) {
    h = __float2bfloat16(x);
    l = __float2bfloat16(x - __bfloat162float(h));
}
__device__ __forceinline__ uint32_t smem_u32(const void* p) {
    return (uint32_t)__cvta_generic_to_shared(p);
}
__device__ __forceinline__ void ldm_x4(uint32_t addr, uint32_t r[4]) {
    asm volatile("ldmatrix.sync.aligned.m8n8.x4.shared.b16 {%0,%1,%2,%3}, [%4];"
                 : "=r"(r[0]), "=r"(r[1]), "=r"(r[2]), "=r"(r[3]) : "r"(addr));
}
__device__ __forceinline__ void ldm_x2(uint32_t addr, uint32_t r[2]) {
    asm volatile("ldmatrix.sync.aligned.m8n8.x2.shared.b16 {%0,%1}, [%2];"
                 : "=r"(r[0]), "=r"(r[1]) : "r"(addr));
}
__device__ __forceinline__ void mma16816(float d[4], const uint32_t a[4], const uint32_t b[2]) {
    asm volatile("mma.sync.aligned.m16n8k16.row.col.f32.bf16.bf16.f32 "
                 "{%0,%1,%2,%3}, {%4,%5,%6,%7}, {%8,%9}, {%0,%1,%2,%3};"
                 : "+f"(d[0]), "+f"(d[1]), "+f"(d[2]), "+f"(d[3])
                 : "r"(a[0]), "r"(a[1]), "r"(a[2]), "r"(a[3]), "r"(b[0]), "r"(b[1]));
}

constexpr int PAD = 40;  // bf16 row stride: 80 bytes (conflict-free ldmatrix)

// ---------------- generic batched GEMM with register double-buffer prefetch ----------------
__global__ __launch_bounds__(256, 2) void gemm_bf3(
    const float* __restrict__ A, const float* __restrict__ W,
    const float* __restrict__ bias, float* __restrict__ C,
    int M, int N, int K, int kchunks, int relu)
{
    __shared__ __nv_bfloat16 sAh[64 * PAD], sAl[64 * PAD];
    __shared__ __nv_bfloat16 sWh[128 * PAD], sWl[128 * PAD];

    const int bm = blockIdx.y * 64;
    const int bn = blockIdx.x * 128;
    const int z  = blockIdx.z;
    const int Kc = K / kchunks;
    const int tid  = threadIdx.x;
    const int lane = tid & 31, warp = tid >> 5;
    const int wm = (warp & 1) * 32;
    const int wn = (warp >> 1) * 32;

    float acc[2][4][4];
#pragma unroll
    for (int mi = 0; mi < 2; mi++)
#pragma unroll
        for (int ni = 0; ni < 4; ni++)
#pragma unroll
            for (int e = 0; e < 4; e++) acc[mi][ni][e] = 0.0f;

    // per-thread staging coordinates: row = f>>3, col = (f&7)*4
    const int rowA0 = tid >> 3, rowA1 = (tid + 256) >> 3;
    const int colS  = (tid & 7) * 4;
    const float* pA0 = A + (size_t)(bm + rowA0) * K + (size_t)z * Kc + colS;
    const float* pA1 = A + (size_t)(bm + rowA1) * K + (size_t)z * Kc + colS;
    const float* pW[4];
#pragma unroll
    for (int i = 0; i < 4; i++) {
        int r = (tid + i * 256) >> 3;
        pW[i] = W + (size_t)(bn + r) * K + (size_t)z * Kc + colS;
    }

    const int arow = lane & 15, acol8 = (lane >> 4) * 8;
    const int brow = lane & 7,  bcol8 = ((lane >> 3) & 1) * 8;

    // preload tile 0
    float4 ra[2], rw[4];
    ra[0] = *(const float4*)pA0;
    ra[1] = *(const float4*)pA1;
#pragma unroll
    for (int i = 0; i < 4; i++) rw[i] = *(const float4*)pW[i];

    for (int kt = 0; kt < Kc; kt += 32) {
        // stage current regs -> smem (bsplit)
        {
            int r0 = rowA0, r1 = rowA1;
            bsplit(ra[0].x, sAh[r0 * PAD + colS + 0], sAl[r0 * PAD + colS + 0]);
            bsplit(ra[0].y, sAh[r0 * PAD + colS + 1], sAl[r0 * PAD + colS + 1]);
            bsplit(ra[0].z, sAh[r0 * PAD + colS + 2], sAl[r0 * PAD + colS + 2]);
            bsplit(ra[0].w, sAh[r0 * PAD + colS + 3], sAl[r0 * PAD + colS + 3]);
            bsplit(ra[1].x, sAh[r1 * PAD + colS + 0], sAl[r1 * PAD + colS + 0]);
            bsplit(ra[1].y, sAh[r1 * PAD + colS + 1], sAl[r1 * PAD + colS + 1]);
            bsplit(ra[1].z, sAh[r1 * PAD + colS + 2], sAl[r1 * PAD + colS + 2]);
            bsplit(ra[1].w, sAh[r1 * PAD + colS + 3], sAl[r1 * PAD + colS + 3]);
#pragma unroll
            for (int i = 0; i < 4; i++) {
                int r = (tid + i * 256) >> 3;
                bsplit(rw[i].x, sWh[r * PAD + colS + 0], sWl[r * PAD + colS + 0]);
                bsplit(rw[i].y, sWh[r * PAD + colS + 1], sWl[r * PAD + colS + 1]);
                bsplit(rw[i].z, sWh[r * PAD + colS + 2], sWl[r * PAD + colS + 2]);
                bsplit(rw[i].w, sWh[r * PAD + colS + 3], sWl[r * PAD + colS + 3]);
            }
        }
        __syncthreads();

        // prefetch next tile (overlaps with mma below)
        if (kt + 32 < Kc) {
            ra[0] = *(const float4*)(pA0 + kt + 32);
            ra[1] = *(const float4*)(pA1 + kt + 32);
#pragma unroll
            for (int i = 0; i < 4; i++) rw[i] = *(const float4*)(pW[i] + kt + 32);
        }

#pragma unroll
        for (int ks = 0; ks < 32; ks += 16) {
            uint32_t ah[2][4], al[2][4], bh[4][2], bl[4][2];
#pragma unroll
            for (int mi = 0; mi < 2; mi++) {
                int r = wm + mi * 16 + arow, c = ks + acol8;
                ldm_x4(smem_u32(&sAh[r * PAD + c]), ah[mi]);
                ldm_x4(smem_u32(&sAl[r * PAD + c]), al[mi]);
            }
#pragma unroll
            for (int ni = 0; ni < 4; ni++) {
                int r = wn + ni * 8 + brow, c = ks + bcol8;
                ldm_x2(smem_u32(&sWh[r * PAD + c]), bh[ni]);
                ldm_x2(smem_u32(&sWl[r * PAD + c]), bl[ni]);
            }
#pragma unroll
            for (int mi = 0; mi < 2; mi++)
#pragma unroll
                for (int ni = 0; ni < 4; ni++) {
                    mma16816(acc[mi][ni], ah[mi], bh[ni]);
                    mma16816(acc[mi][ni], al[mi], bh[ni]);
                    mma16816(acc[mi][ni], ah[mi], bl[ni]);
                }
        }
        __syncthreads();
    }

    float* Cz = C + (size_t)z * ((size_t)M * N);
    const int mr = lane >> 2;
    const int nc = (lane & 3) * 2;
#pragma unroll
    for (int mi = 0; mi < 2; mi++)
#pragma unroll
        for (int ni = 0; ni < 4; ni++) {
            int m0 = bm + wm + mi * 16 + mr;
            int n0 = bn + wn + ni * 8 + nc;
            float2 v0 = make_float2(acc[mi][ni][0], acc[mi][ni][1]);
            float2 v1 = make_float2(acc[mi][ni][2], acc[mi][ni][3]);
            if (kchunks == 1) {
                if (bias) {
                    float b0v = bias[n0], b1v = bias[n0 + 1];
                    v0.x += b0v; v0.y += b1v; v1.x += b0v; v1.y += b1v;
                }
                if (relu) {
                    v0.x = fmaxf(v0.x, 0.0f); v0.y = fmaxf(v0.y, 0.0f);
                    v1.x = fmaxf(v1.x, 0.0f); v1.y = fmaxf(v1.y, 0.0f);
                }
            }
            *(float2*)(Cz + (size_t)m0 * N + n0) = v0;
            *(float2*)(Cz + (size_t)(m0 + 8) * N + n0) = v1;
        }
}

// ---------------- fused persistent LSTM layer (with prefetch) ----------------
constexpr int LSTM_NBLK = 128;
constexpr int SM_WHI = 0;                    // 16 iters * 16 rows * 40 * 2B = 20480
constexpr int SM_WLO = 20480;
constexpr int SM_AHI = 40960;                // 64 * 40 * 2B = 5120
constexpr int SM_ALO = 46080;
constexpr int SM_P   = 51200;                // 64*16 fp32 = 4096
constexpr int SM_C   = 55296;                // 256 fp32 = 1024
constexpr int SM_TOTAL_LSTM = 56320;

__device__ __forceinline__ void grid_bar() {
    __syncthreads();
    if (threadIdx.x == 0) {
        __threadfence();
        unsigned gen = *((volatile unsigned*)&g_bar_gen);
        if (atomicAdd(&g_bar_cnt, 1) == LSTM_NBLK - 1) {
            atomicExch(&g_bar_cnt, 0);
            __threadfence();
            atomicExch(&g_bar_gen, gen + 1);
        } else {
            while (*((volatile unsigned*)&g_bar_gen) == gen) __nanosleep(32);
        }
        __threadfence();
    }
    __syncthreads();
}

__global__ __launch_bounds__(256, 1) void fused_lstm(
    const __nv_bfloat16* __restrict__ WHI, const __nv_bfloat16* __restrict__ WLO,
    const float* __restrict__ XG, const float* __restrict__ h0s,
    const float* __restrict__ c0s, float* __restrict__ HSEQ,
    float* __restrict__ HB0, float* __restrict__ HB1)
{
    extern __shared__ char smem[];
    __nv_bfloat16* sWh = (__nv_bfloat16*)(smem + SM_WHI);
    __nv_bfloat16* sWl = (__nv_bfloat16*)(smem + SM_WLO);
    __nv_bfloat16* sAh = (__nv_bfloat16*)(smem + SM_AHI);
    __nv_bfloat16* sAl = (__nv_bfloat16*)(smem + SM_ALO);
    float* P   = (float*)(smem + SM_P);
    float* csh = (float*)(smem + SM_C);

    const int j = blockIdx.x;
    const int tid = threadIdx.x;
    const int lane = tid & 31, warp = tid >> 5;
    const int wm = (warp & 3) * 16;   // 4 warps along M (batches)
    const int wn = (warp >> 2) * 8;   // 2 warps along N (gate cols)

    // gather Whh slice: 16 gate rows x 512 -> chunked smem [it][16][40]
    for (int idx = tid; idx < 16 * 512; idx += 256) {
        int n = idx >> 9, k = idx & 511;
        int grow = (n >> 2) * 512 + j * 4 + (n & 3);
        int so = (k >> 5) * 640 + n * 40 + (k & 31);
        sWh[so] = WHI[(size_t)grow * 512 + k];
        sWl[so] = WLO[(size_t)grow * 512 + k];
    }
    // init c state + H(0)
    const int gb = tid >> 2, gu = tid & 3;
    const int gcol = j * 4 + gu;
    csh[tid] = c0s[gb * 512 + gcol];
    HB0[gb * 512 + gcol] = h0s[gb * 512 + gcol];
    __threadfence();
    grid_bar();

    const int arow = lane & 15, acol8 = (lane >> 4) * 8;
    const int brow = lane & 7,  bcol8 = ((lane >> 3) & 1) * 8;

    // per-thread H staging coords
    const int hr0 = tid >> 3, hr1 = (tid + 256) >> 3;
    const int hc  = (tid & 7) * 4;

    for (int t = 0; t < 24; t++) {
        const float* Hin = (t & 1) ? HB1 : HB0;
        float* Hout      = (t & 1) ? HB0 : HB1;

        // prefetch XG gate row early (independent of H)
        const float* xgp = XG + (size_t)(gb * 24 + t) * 2048 + gcol;
        float xg_i = __ldg(xgp);
        float xg_f = __ldg(xgp + 512);
        float xg_g = __ldg(xgp + 1024);
        float xg_o = __ldg(xgp + 1536);

        float acc[4] = {0.0f, 0.0f, 0.0f, 0.0f};

        // preload chunk 0
        float4 h4a = __ldcg((const float4*)(Hin + hr0 * 512 + hc));
        float4 h4b = __ldcg((const float4*)(Hin + hr1 * 512 + hc));

        for (int it = 0; it < 16; it++) {
            // stage current chunk regs -> smem
            bsplit(h4a.x, sAh[hr0 * PAD + hc + 0], sAl[hr0 * PAD + hc + 0]);
            bsplit(h4a.y, sAh[hr0 * PAD + hc + 1], sAl[hr0 * PAD + hc + 1]);
            bsplit(h4a.z, sAh[hr0 * PAD + hc + 2], sAl[hr0 * PAD + hc + 2]);
            bsplit(h4a.w, sAh[hr0 * PAD + hc + 3], sAl[hr0 * PAD + hc + 3]);
            bsplit(h4b.x, sAh[hr1 * PAD + hc + 0], sAl[hr1 * PAD + hc + 0]);
            bsplit(h4b.y, sAh[hr1 * PAD + hc + 1], sAl[hr1 * PAD + hc + 1]);
            bsplit(h4b.z, sAh[hr1 * PAD + hc + 2], sAl[hr1 * PAD + hc + 2]);
            bsplit(h4b.w, sAh[hr1 * PAD + hc + 3], sAl[hr1 * PAD + hc + 3]);
            __syncthreads();

            // prefetch next chunk (overlaps mma)
            if (it + 1 < 16) {
                int kn = (it + 1) * 32;
                h4a = __ldcg((const float4*)(Hin + hr0 * 512 + kn + hc));
                h4b = __ldcg((const float4*)(Hin + hr1 * 512 + kn + hc));
            }

            const __nv_bfloat16* wh = sWh + it * 640;
            const __nv_bfloat16* wl = sWl + it * 640;
#pragma unroll
            for (int ks = 0; ks < 32; ks += 16) {
                uint32_t ah[4], al[4], bh[2], bl[2];
                ldm_x4(smem_u32(&sAh[(wm + arow) * PAD + ks + acol8]), ah);
                ldm_x4(smem_u32(&sAl[(wm + arow) * PAD + ks + acol8]), al);
                ldm_x2(smem_u32(&wh[(wn + brow) * PAD + ks + bcol8]), bh);
                ldm_x2(smem_u32(&wl[(wn + brow) * PAD + ks + bcol8]), bl);
                mma16816(acc, ah, bh);
                mma16816(acc, al, bh);
                mma16816(acc, ah, bl);
            }
            __syncthreads();
        }

        // write pre-activations to smem P [64][16]
        {
            int r0 = wm + (lane >> 2);
            int c0 = wn + (lane & 3) * 2;
            P[r0 * 16 + c0] = acc[0];       P[r0 * 16 + c0 + 1] = acc[1];
            P[(r0 + 8) * 16 + c0] = acc[2]; P[(r0 + 8) * 16 + c0 + 1] = acc[3];
        }
        __syncthreads();

        // gate update: thread -> (batch gb, unit gu)
        {
            float gi = P[gb * 16 + gu]      + xg_i;
            float gf = P[gb * 16 + 4 + gu]  + xg_f;
            float gg = P[gb * 16 + 8 + gu]  + xg_g;
            float go = P[gb * 16 + 12 + gu] + xg_o;
            float c = sigmoidf_(gf) * csh[tid] + sigmoidf_(gi) * tanhf(gg);
            csh[tid] = c;
            float hn = sigmoidf_(go) * tanhf(c);
            Hout[gb * 512 + gcol] = hn;
            HSEQ[(size_t)(gb * 24 + t) * 512 + gcol] = hn;
        }
        __threadfence();
        grid_bar();
    }
}

// split fp32 weights to bf16 hi/lo
__global__ void split_w(const float* __restrict__ W, __nv_bfloat16* __restrict__ HI,
                        __nv_bfloat16* __restrict__ LO, int n)
{
    int i = blockIdx.x * blockDim.x + threadIdx.x;
    if (i >= n) return;
    __nv_bfloat16 h, l;
    bsplit(W[i], h, l);
    HI[i] = h; LO[i] = l;
}

// sum split-K partials + bias + optional relu
__global__ void reduce_bias_act(const float* __restrict__ GP, const float* __restrict__ bias,
                                float* __restrict__ out, int total, int N, int kchunks, int relu)
{
    int i = blockIdx.x * blockDim.x + threadIdx.x;
    if (i >= total) return;
    float s = 0.0f;
    for (int z = 0; z < kchunks; z++) s += GP[(size_t)z * total + i];
    if (bias) s += bias[i % N];
    if (relu) s = fmaxf(s, 0.0f);
    out[i] = s;
}

__global__ void ae_post(const float* __restrict__ x, const float* __restrict__ AUTO,
                        float* __restrict__ NEWX, float* __restrict__ outAuto)
{
    int i = blockIdx.x * blockDim.x + threadIdx.x;
    if (i >= 786432) return;
    float xv = x[i], av = AUTO[i];
    NEWX[i] = xv;
    NEWX[786432 + i] = xv - av;
    outAuto[i] = av;
}

__global__ void permute_lstm_in(const float* __restrict__ OUT1, float* __restrict__ LSTMIN)
{
    int f = blockIdx.x * blockDim.x + threadIdx.x;
    if (f >= 786432) return;
    int s  = f >> 15;
    int b2 = (f >> 8) & 127;
    int g  = f & 255;
    LSTMIN[f] = OUT1[(size_t)b2 * 6144 + s * 256 + g];
}

__global__ void comb_bias(const float* __restrict__ bih0, const float* __restrict__ bhh0,
                          const float* __restrict__ bih1, const float* __restrict__ bhh1,
                          float* __restrict__ B0, float* __restrict__ B1)
{
    int i = blockIdx.x * blockDim.x + threadIdx.x;
    if (i >= 2048) return;
    B0[i] = bih0[i] + bhh0[i];
    B1[i] = bih1[i] + bhh1[i];
}

__global__ void pred_fc(const float* __restrict__ HSEQ1, const float* __restrict__ lfcW,
                        const float* __restrict__ lfcb, float* __restrict__ NF)
{
    __shared__ float hrow[512];
    int b = blockIdx.x / 12;
    int p = blockIdx.x % 12;
    int row = b * 24 + 12 + p;
    int tid = threadIdx.x;  // 128 threads
    *(float4*)(&hrow[tid * 4]) = *(const float4*)(HSEQ1 + (size_t)row * 512 + tid * 4);
    __syncthreads();
    float acc = lfcb[tid];
    const float* wr = lfcW + (size_t)tid * 512;
#pragma unroll 8
    for (int k = 0; k < 512; k++) acc += hrow[k] * wr[k];
    NF[(size_t)b * 2560 + p * 128 + tid] = acc;
}

__global__ void concat_hidden(const float* __restrict__ HID, float* __restrict__ NF)
{
    int i = blockIdx.x * blockDim.x + threadIdx.x;
    if (i >= 65536) return;
    int b = i >> 10, j = i & 1023;
    NF[(size_t)b * 2560 + 1536 + j] = HID[i];
}

// ---------------- host launch sequence ----------------
extern "C" void kernel_launch(void* const* d_in, const int* in_sizes, int n_in,
                              void* d_out, int out_size)
{
    (void)in_sizes; (void)n_in; (void)out_size;
    const float* x     = (const float*)d_in[0];
    const float* adj   = (const float*)d_in[1];
    const float* h0    = (const float*)d_in[2];
    const float* c0    = (const float*)d_in[3];
    const float* fc11W = (const float*)d_in[4];
    const float* fc11b = (const float*)d_in[5];
    const float* fc12W = (const float*)d_in[6];
    const float* fc12b = (const float*)d_in[7];
    const float* fc21W = (const float*)d_in[8];
    const float* fc21b = (const float*)d_in[9];
    const float* fc22W = (const float*)d_in[10];
    const float* fc22b = (const float*)d_in[11];
    const float* gc1W  = (const float*)d_in[12];
    const float* gc1b  = (const float*)d_in[13];
    const float* gc2W  = (const float*)d_in[14];
    const float* gc2b  = (const float*)d_in[15];
    const float* Wih0  = (const float*)d_in[16];
    const float* Whh0  = (const float*)d_in[17];
    const float* bih0  = (const float*)d_in[18];
    const float* bhh0  = (const float*)d_in[19];
    const float* Wih1  = (const float*)d_in[20];
    const float* Whh1  = (const float*)d_in[21];
    const float* bih1  = (const float*)d_in[22];
    const float* bhh1  = (const float*)d_in[23];
    const float* lfcW  = (const float*)d_in[24];
    const float* lfcb  = (const float*)d_in[25];
    const float* fcW   = (const float*)d_in[26];
    const float* fcb   = (const float*)d_in[27];

    float* out = (float*)d_out;          // [64,12,512]
    float* outAuto = out + 393216;       // [64,24,512]

    float* Sc;
    cudaGetSymbolAddress((void**)&Sc, g_scratch);
    float* T1     = Sc + OFF_T1;
    float* HID    = Sc + OFF_HID;
    float* T2     = Sc + OFF_T2;
    float* AUTO   = Sc + OFF_AUTO;
    float* NEWX   = Sc + OFF_NEWX;
    float* M1     = Sc + OFF_M1;
    float* H1     = Sc + OFF_H1;
    float* M2     = Sc + OFF_M2;
    float* OUT1   = Sc + OFF_OUT1;
    float* LSTMIN = Sc + OFF_LSTMIN;
    float* XG     = Sc + OFF_XG;
    float* HSEQ0  = Sc + OFF_HSEQ0;
    float* HSEQ1  = Sc + OFF_HSEQ1;
    float* HA     = Sc + OFF_HA;
    float* HB     = Sc + OFF_HB;
    float* NF     = Sc + OFF_NF;
    float* B0     = Sc + OFF_B0;
    float* B1     = Sc + OFF_B1;
    float* GP     = Sc + OFF_GP;
    __nv_bfloat16* W0HI = (__nv_bfloat16*)(Sc + OFF_W0HI);
    __nv_bfloat16* W0LO = (__nv_bfloat16*)(Sc + OFF_W0LO);
    __nv_bfloat16* W1HI = (__nv_bfloat16*)(Sc + OFF_W1HI);
    __nv_bfloat16* W1LO = (__nv_bfloat16*)(Sc + OFF_W1LO);

    static bool attr_set = false;
    if (!attr_set) {
        cudaFuncSetAttribute(fused_lstm, cudaFuncAttributeMaxDynamicSharedMemorySize,
                             SM_TOTAL_LSTM);
        attr_set = true;
    }

    // ---- weight prep (independent) ----
    split_w<<<4096, 256>>>(Whh0, W0HI, W0LO, 2048 * 512);
    split_w<<<4096, 256>>>(Whh1, W1HI, W1LO, 2048 * 512);
    comb_bias<<<8, 256>>>(bih0, bhh0, bih1, bhh1, B0, B1);

    // ---- AutoEncoder ----
    gemm_bf3<<<dim3(32, 1, 16), 256>>>(x, fc11W, nullptr, GP, 64, 4096, 12288, 16, 0);
    reduce_bias_act<<<1024, 256>>>(GP, fc11b, T1, 262144, 4096, 16, 1);
    gemm_bf3<<<dim3(8, 1, 16), 256>>>(T1, fc12W, nullptr, GP, 64, 1024, 4096, 16, 0);
    reduce_bias_act<<<256, 256>>>(GP, fc12b, HID, 65536, 1024, 16, 1);
    gemm_bf3<<<dim3(32, 1, 8), 256>>>(HID, fc21W, nullptr, GP, 64, 4096, 1024, 8, 0);
    reduce_bias_act<<<1024, 256>>>(GP, fc21b, T2, 262144, 4096, 8, 1);
    gemm_bf3<<<dim3(96, 1, 4), 256>>>(T2, fc22W, nullptr, GP, 64, 12288, 4096, 4, 0);
    reduce_bias_act<<<3072, 256>>>(GP, fc22b, AUTO, 786432, 12288, 4, 1);
    ae_post<<<3072, 256>>>(x, AUTO, NEWX, outAuto);

    // ---- GCN ----
    gemm_bf3<<<dim3(4, 48, 1), 256>>>(NEWX, adj, nullptr, M1, 3072, 512, 512, 1, 0);
    gemm_bf3<<<dim3(4, 48, 1), 256>>>(M1, gc1W, gc1b, H1, 3072, 512, 512, 1, 1);
    gemm_bf3<<<dim3(4, 48, 1), 256>>>(H1, adj, nullptr, M2, 3072, 512, 512, 1, 0);
    gemm_bf3<<<dim3(2, 48, 1), 256>>>(M2, gc2W, gc2b, OUT1, 3072, 256, 512, 1, 0);
    permute_lstm_in<<<3072, 256>>>(OUT1, LSTMIN);

    // ---- LSTM (fused persistent kernels with prefetch) ----
    gemm_bf3<<<dim3(16, 24, 1), 256>>>(LSTMIN, Wih0, B0, XG, 1536, 2048, 512, 1, 0);
    fused_lstm<<<LSTM_NBLK, 256, SM_TOTAL_LSTM>>>(W0HI, W0LO, XG, h0, c0, HSEQ0, HA, HB);
    gemm_bf3<<<dim3(16, 24, 1), 256>>>(HSEQ0, Wih1, B1, XG, 1536, 2048, 512, 1, 0);
    fused_lstm<<<LSTM_NBLK, 256, SM_TOTAL_LSTM>>>(W1HI, W1LO, XG, h0 + 32768, c0 + 32768,
                                                  HSEQ1, HA, HB);

    // ---- head ----
    pred_fc<<<768, 128>>>(HSEQ1, lfcW, lfcb, NF);
    concat_hidden<<<256, 256>>>(HID, NF);
    gemm_bf3<<<dim3(48, 1, 4), 256>>>(NF, fcW, nullptr, GP, 64, 6144, 2560, 4, 0);
    reduce_bias_act<<<1536, 256>>>(GP, fcb, out, 393216, 6144, 4, 0);
}

// round 9
// speedup vs baseline: 1.3059x; 1.2238x over previous
#include <cuda_runtime.h>
#include <cuda_bf16.h>
#include <math.h>
#include <stdint.h>

constexpr size_t OFF_T1     = 0;
constexpr size_t OFF_HID    = OFF_T1     + 262144;
constexpr size_t OFF_T2     = OFF_HID    + 65536;
constexpr size_t OFF_AUTO   = OFF_T2     + 262144;
constexpr size_t OFF_NEWX   = OFF_AUTO   + 786432;
constexpr size_t OFF_M1     = OFF_NEWX   + 1572864;
constexpr size_t OFF_H1     = OFF_M1     + 1572864;
constexpr size_t OFF_M2     = OFF_H1     + 1572864;
constexpr size_t OFF_OUT1   = OFF_M2     + 1572864;
constexpr size_t OFF_LSTMIN = OFF_OUT1   + 786432;
constexpr size_t OFF_XG     = OFF_LSTMIN + 786432;
constexpr size_t OFF_HSEQ0  = OFF_XG     + 3145728;
constexpr size_t OFF_HSEQ1  = OFF_HSEQ0  + 786432;
constexpr size_t OFF_HA     = OFF_HSEQ1  + 786432;
constexpr size_t OFF_HB     = OFF_HA     + 32768;
constexpr size_t OFF_NF     = OFF_HB     + 32768;
constexpr size_t OFF_B0     = OFF_NF     + 163840;
constexpr size_t OFF_B1     = OFF_B0     + 2048;
constexpr size_t OFF_W0HI   = OFF_B1     + 2048;
constexpr size_t OFF_W0LO   = OFF_W0HI   + 524288;
constexpr size_t OFF_W1HI   = OFF_W0LO   + 524288;
constexpr size_t OFF_W1LO   = OFF_W1HI   + 524288;
constexpr size_t OFF_GP     = OFF_W1LO   + 524288;
constexpr size_t TOTAL_SCRATCH = OFF_GP  + 8388608;

__device__ float g_scratch[TOTAL_SCRATCH];
__device__ unsigned g_bar_cnt = 0;
__device__ unsigned g_bar_gen = 0;

__device__ __forceinline__ float sigmoidf_(float v) { return 1.0f / (1.0f + expf(-v)); }

__device__ __forceinline__ void bsplit(float x, __nv_bfloat16& h, __nv_bfloat16& l) {
    h = __float2bfloat16(x);
    l = __float2bfloat16(x - __bfloat162float(h));
}

// two floats -> bf16x2 hi (truncation) + bf16x2 lo (exact residual)
__device__ __forceinline__ void cvt_pair(float2 f, uint32_t& hi, uint32_t& lo) {
    uint32_t xb = __float_as_uint(f.x), yb = __float_as_uint(f.y);
    hi = __byte_perm(xb, yb, 0x7632);
    float lx = f.x - __uint_as_float(xb & 0xFFFF0000u);
    float ly = f.y - __uint_as_float(yb & 0xFFFF0000u);
    __nv_bfloat162 l2 = __floats2bfloat162_rn(lx, ly);
    lo = *(uint32_t*)&l2;
}

__device__ __forceinline__ void cvt4_store(float4 v, __nv_bfloat16* ph, __nv_bfloat16* pl) {
    uint32_t xb = __float_as_uint(v.x), yb = __float_as_uint(v.y);
    uint32_t zb = __float_as_uint(v.z), wb = __float_as_uint(v.w);
    ((uint32_t*)ph)[0] = __byte_perm(xb, yb, 0x7632);
    ((uint32_t*)ph)[1] = __byte_perm(zb, wb, 0x7632);
    float lx = v.x - __uint_as_float(xb & 0xFFFF0000u);
    float ly = v.y - __uint_as_float(yb & 0xFFFF0000u);
    float lz = v.z - __uint_as_float(zb & 0xFFFF0000u);
    float lw = v.w - __uint_as_float(wb & 0xFFFF0000u);
    __nv_bfloat162 l01 = __floats2bfloat162_rn(lx, ly);
    __nv_bfloat162 l23 = __floats2bfloat162_rn(lz, lw);
    ((uint32_t*)pl)[0] = *(uint32_t*)&l01;
    ((uint32_t*)pl)[1] = *(uint32_t*)&l23;
}

__device__ __forceinline__ uint32_t smem_u32(const void* p) {
    return (uint32_t)__cvta_generic_to_shared(p);
}
__device__ __forceinline__ void ldm_x4(uint32_t addr, uint32_t r[4]) {
    asm volatile("ldmatrix.sync.aligned.m8n8.x4.shared.b16 {%0,%1,%2,%3}, [%4];"
                 : "=r"(r[0]), "=r"(r[1]), "=r"(r[2]), "=r"(r[3]) : "r"(addr));
}
__device__ __forceinline__ void ldm_x2(uint32_t addr, uint32_t r[2]) {
    asm volatile("ldmatrix.sync.aligned.m8n8.x2.shared.b16 {%0,%1}, [%2];"
                 : "=r"(r[0]), "=r"(r[1]) : "r"(addr));
}
__device__ __forceinline__ void mma16816(float d[4], const uint32_t a[4], const uint32_t b[2]) {
    asm volatile("mma.sync.aligned.m16n8k16.row.col.f32.bf16.bf16.f32 "
                 "{%0,%1,%2,%3}, {%4,%5,%6,%7}, {%8,%9}, {%0,%1,%2,%3};"
                 : "+f"(d[0]), "+f"(d[1]), "+f"(d[2]), "+f"(d[3])
                 : "r"(a[0]), "r"(a[1]), "r"(a[2]), "r"(a[3]), "r"(b[0]), "r"(b[1]));
}

// GEMM: C = act(A[M,K] * W[N,K]^T + bias). W streams gmem->regs in fragment layout.
constexpr int GPAD = 72;

__global__ __launch_bounds__(256, 2) void gemm_bf3(
    const float* __restrict__ A, const float* __restrict__ W,
    const float* __restrict__ bias, float* __restrict__ C,
    int M, int N, int K, int kchunks, int relu)
{
    __shared__ __align__(16) __nv_bfloat16 sAh[64 * GPAD];
    __shared__ __align__(16) __nv_bfloat16 sAl[64 * GPAD];

    const int bm = blockIdx.y * 64;
    const int bn = blockIdx.x * 128;
    const int z  = blockIdx.z;
    const int Kc = K / kchunks;
    const int NC = Kc >> 6;
    const int tid  = threadIdx.x;
    const int lane = tid & 31, warp = tid >> 5;
    const int wm = (warp & 1) * 32;
    const int wn = (warp >> 1) * 32;

    float acc[2][4][4];
#pragma unroll
    for (int mi = 0; mi < 2; mi++)
#pragma unroll
        for (int ni = 0; ni < 4; ni++)
#pragma unroll
            for (int e = 0; e < 4; e++) acc[mi][ni][e] = 0.0f;

    const int scol = (tid & 15) * 4;
    const float* Ap[4];
#pragma unroll
    for (int i = 0; i < 4; i++)
        Ap[i] = A + (size_t)(bm + i * 16 + (tid >> 4)) * K + (size_t)z * Kc + scol;

    const float* wp[4];
#pragma unroll
    for (int ni = 0; ni < 4; ni++)
        wp[ni] = W + (size_t)(bn + wn + ni * 8 + (lane >> 2)) * K + (size_t)z * Kc + (lane & 3) * 2;

    const int arow = lane & 15, acol8 = (lane >> 4) * 8;

    float4 ar[4];
#pragma unroll
    for (int i = 0; i < 4; i++) ar[i] = *(const float4*)(Ap[i]);

    float2 wr0[4][2], wr1[4][2];
#pragma unroll
    for (int ni = 0; ni < 4; ni++) {
        wr0[ni][0] = *(const float2*)(wp[ni] + 0);
        wr0[ni][1] = *(const float2*)(wp[ni] + 8);
        wr1[ni][0] = *(const float2*)(wp[ni] + 16);
        wr1[ni][1] = *(const float2*)(wp[ni] + 24);
    }

    auto step = [&](float2 (&wb)[4][2], int c, int s) {
        uint32_t bh[4][2], bl[4][2];
#pragma unroll
        for (int ni = 0; ni < 4; ni++) {
            cvt_pair(wb[ni][0], bh[ni][0], bl[ni][0]);
            cvt_pair(wb[ni][1], bh[ni][1], bl[ni][1]);
        }
        int g16 = (c * 4 + s + 2) * 16;
        if (g16 < Kc) {
#pragma unroll
            for (int ni = 0; ni < 4; ni++) {
                wb[ni][0] = *(const float2*)(wp[ni] + g16);
                wb[ni][1] = *(const float2*)(wp[ni] + g16 + 8);
            }
        }
        uint32_t ah[2][4], al[2][4];
        const int colb = s * 16;
#pragma unroll
        for (int mi = 0; mi < 2; mi++) {
            int r = wm + mi * 16 + arow;
            ldm_x4(smem_u32(&sAh[r * GPAD + colb + acol8]), ah[mi]);
            ldm_x4(smem_u32(&sAl[r * GPAD + colb + acol8]), al[mi]);
        }
#pragma unroll
        for (int mi = 0; mi < 2; mi++)
#pragma unroll
            for (int ni = 0; ni < 4; ni++) {
                mma16816(acc[mi][ni], ah[mi], bh[ni]);
                mma16816(acc[mi][ni], al[mi], bh[ni]);
                mma16816(acc[mi][ni], ah[mi], bl[ni]);
            }
    };

    for (int c = 0; c < NC; c++) {
        __syncthreads();
#pragma unroll
        for (int i = 0; i < 4; i++) {
            int r = i * 16 + (tid >> 4);
            cvt4_store(ar[i], &sAh[r * GPAD + scol], &sAl[r * GPAD + scol]);
        }
        __syncthreads();
        if (c + 1 < NC) {
            int off = (c + 1) * 64;
#pragma unroll
            for (int i = 0; i < 4; i++) ar[i] = *(const float4*)(Ap[i] + off);
        }
        step(wr0, c, 0);
        step(wr1, c, 1);
        step(wr0, c, 2);
        step(wr1, c, 3);
    }

    float* Cz = C + (size_t)z * ((size_t)M * N);
    const int mr = lane >> 2;
    const int nc = (lane & 3) * 2;
#pragma unroll
    for (int mi = 0; mi < 2; mi++)
#pragma unroll
        for (int ni = 0; ni < 4; ni++) {
            int m0 = bm + wm + mi * 16 + mr;
            int n0 = bn + wn + ni * 8 + nc;
            float2 v0 = make_float2(acc[mi][ni][0], acc[mi][ni][1]);
            float2 v1 = make_float2(acc[mi][ni][2], acc[mi][ni][3]);
            if (kchunks == 1) {
                if (bias) {
                    float b0v = bias[n0], b1v = bias[n0 + 1];
                    v0.x += b0v; v0.y += b1v; v1.x += b0v; v1.y += b1v;
                }
                if (relu) {
                    v0.x = fmaxf(v0.x, 0.0f); v0.y = fmaxf(v0.y, 0.0f);
                    v1.x = fmaxf(v1.x, 0.0f); v1.y = fmaxf(v1.y, 0.0f);
                }
            }
            *(float2*)(Cz + (size_t)m0 * N + n0) = v0;
            *(float2*)(Cz + (size_t)(m0 + 8) * N + n0) = v1;
        }
}

// fused persistent LSTM
constexpr int LSTM_NBLK = 128;
constexpr int LPAD = 136;
constexpr int LSM_WHI = 0;
constexpr int LSM_WLO = LSM_WHI + 4 * 16 * LPAD * 2;
constexpr int LSM_AHI = LSM_WLO + 4 * 16 * LPAD * 2;
constexpr int LSM_ALO = LSM_AHI + 64 * LPAD * 2;
constexpr int LSM_P   = LSM_ALO + 64 * LPAD * 2;
constexpr int LSM_C   = LSM_P + 64 * 16 * 4;
constexpr int SM_TOTAL_LSTM = LSM_C + 1024;

__device__ __forceinline__ void grid_bar_full() {
    __syncthreads();
    if (threadIdx.x == 0) {
        __threadfence();
        unsigned gen = *((volatile unsigned*)&g_bar_gen);
        if (atomicAdd(&g_bar_cnt, 1) == LSTM_NBLK - 1) {
            atomicExch(&g_bar_cnt, 0);
            __threadfence();
            atomicExch(&g_bar_gen, gen + 1);
        } else {
            while (*((volatile unsigned*)&g_bar_gen) == gen) __nanosleep(32);
        }
        __threadfence();
    }
    __syncthreads();
}

__global__ __launch_bounds__(256, 1) void fused_lstm(
    const __nv_bfloat16* __restrict__ WHI, const __nv_bfloat16* __restrict__ WLO,
    const float* __restrict__ XG, const float* __restrict__ h0s,
    const float* __restrict__ c0s, float* __restrict__ HSEQ,
    float* __restrict__ HB0, float* __restrict__ HB1)
{
    extern __shared__ char smem[];
    __nv_bfloat16* sWh = (__nv_bfloat16*)(smem + LSM_WHI);
    __nv_bfloat16* sWl = (__nv_bfloat16*)(smem + LSM_WLO);
    __nv_bfloat16* sAh = (__nv_bfloat16*)(smem + LSM_AHI);
    __nv_bfloat16* sAl = (__nv_bfloat16*)(smem + LSM_ALO);
    float* P   = (float*)(smem + LSM_P);
    float* csh = (float*)(smem + LSM_C);

    const int j = blockIdx.x;
    const int tid = threadIdx.x;
    const int lane = tid & 31, warp = tid >> 5;
    const int wm = (warp & 3) * 16;
    const int wn = (warp >> 2) * 8;

    for (int idx = tid; idx < 16 * 512; idx += 256) {
        int n = idx >> 9, k = idx & 511;
        int grow = (n >> 2) * 512 + j * 4 + (n & 3);
        int so = (k >> 7) * (16 * LPAD) + n * LPAD + (k & 127);
        sWh[so] = WHI[(size_t)grow * 512 + k];
        sWl[so] = WLO[(size_t)grow * 512 + k];
    }
    const int gb = tid >> 2, gu = tid & 3;
    const int gcol = j * 4 + gu;
    csh[tid] = c0s[gb * 512 + gcol];
    HB0[gb * 512 + gcol] = h0s[gb * 512 + gcol];
    __threadfence();
    grid_bar_full();

    const int arow = lane & 15, acol8 = (lane >> 4) * 8;
    const int brow = lane & 7,  bcol8 = ((lane >> 3) & 1) * 8;

    for (int t = 0; t < 24; t++) {
        const float* Hin = (t & 1) ? HB1 : HB0;
        float* Hout      = (t & 1) ? HB0 : HB1;

        const float* xgp = XG + (size_t)(gb * 24 + t) * 2048 + gcol;
        float xg_i = __ldg(xgp);
        float xg_f = __ldg(xgp + 512);
        float xg_g = __ldg(xgp + 1024);
        float xg_o = __ldg(xgp + 1536);

        float acc[4][4];
#pragma unroll
        for (int a = 0; a < 4; a++)
#pragma unroll
            for (int e = 0; e < 4; e++) acc[a][e] = 0.0f;

        float4 ar[8];
#pragma unroll
        for (int i = 0; i < 8; i++) {
            int f = i * 256 + tid;
            ar[i] = __ldcg((const float4*)(Hin + (f >> 5) * 512 + (f & 31) * 4));
        }

        for (int c = 0; c < 4; c++) {
            __syncthreads();
#pragma unroll
            for (int i = 0; i < 8; i++) {
                int f = i * 256 + tid;
                int r = f >> 5, col = (f & 31) * 4;
                cvt4_store(ar[i], &sAh[r * LPAD + col], &sAl[r * LPAD + col]);
            }
            __syncthreads();
            if (c < 3) {
                int off = (c + 1) * 128;
#pragma unroll
                for (int i = 0; i < 8; i++) {
                    int f = i * 256 + tid;
                    ar[i] = __ldcg((const float4*)(Hin + (f >> 5) * 512 + off + (f & 31) * 4));
                }
            }
            const __nv_bfloat16* wh = sWh + c * (16 * LPAD);
            const __nv_bfloat16* wl = sWl + c * (16 * LPAD);
#pragma unroll
            for (int s = 0; s < 8; s++) {
                const int col = s * 16;
                uint32_t ah[4], al[4], bh[2], bl[2];
                ldm_x4(smem_u32(&sAh[(wm + arow) * LPAD + col + acol8]), ah);
                ldm_x4(smem_u32(&sAl[(wm + arow) * LPAD + col + acol8]), al);
                ldm_x2(smem_u32(&wh[(wn + brow) * LPAD + col + bcol8]), bh);
                ldm_x2(smem_u32(&wl[(wn + brow) * LPAD + col + bcol8]), bl);
                float* a = acc[s & 3];
                mma16816(a, ah, bh);
                mma16816(a, al, bh);
                mma16816(a, ah, bl);
            }
        }

        float r0v = (acc[0][0] + acc[1][0]) + (acc[2][0] + acc[3][0]);
        float r1v = (acc[0][1] + acc[1][1]) + (acc[2][1] + acc[3][1]);
        float r2v = (acc[0][2] + acc[1][2]) + (acc[2][2] + acc[3][2]);
        float r3v = (acc[0][3] + acc[1][3]) + (acc[2][3] + acc[3][3]);
        {
            int pr = wm + (lane >> 2);
            int pc = wn + (lane & 3) * 2;
            P[pr * 16 + pc] = r0v;       P[pr * 16 + pc + 1] = r1v;
            P[(pr + 8) * 16 + pc] = r2v; P[(pr + 8) * 16 + pc + 1] = r3v;
        }
        __syncthreads();

        {
            float gi = P[gb * 16 + gu]      + xg_i;
            float gf = P[gb * 16 + 4 + gu]  + xg_f;
            float gg = P[gb * 16 + 8 + gu]  + xg_g;
            float go = P[gb * 16 + 12 + gu] + xg_o;
            float cc = sigmoidf_(gf) * csh[tid] + sigmoidf_(gi) * tanhf(gg);
            csh[tid] = cc;
            float hn = sigmoidf_(go) * tanhf(cc);
            Hout[gb * 512 + gcol] = hn;
            HSEQ[(size_t)(gb * 24 + t) * 512 + gcol] = hn;
        }
        __threadfence();
        grid_bar_full();
    }
}

__global__ void split_w(const float* __restrict__ W, __nv_bfloat16* __restrict__ HI,
                        __nv_bfloat16* __restrict__ LO, int n)
{
    int i = blockIdx.x * blockDim.x + threadIdx.x;
    if (i >= n) return;
    __nv_bfloat16 h, l;
    bsplit(W[i], h, l);
    HI[i] = h; LO[i] = l;
}

__global__ void reduce_bias_act(const float* __restrict__ GP, const float* __restrict__ bias,
                                float* __restrict__ out, int total, int N, int kchunks, int relu)
{
    int i = blockIdx.x * blockDim.x + threadIdx.x;
    if (i >= total) return;
    float s = 0.0f;
    for (int z = 0; z < kchunks; z++) s += GP[(size_t)z * total + i];
    if (bias) s += bias[i % N];
    if (relu) s = fmaxf(s, 0.0f);
    out[i] = s;
}

__global__ void ae_post(const float* __restrict__ x, const float* __restrict__ AUTO,
                        float* __restrict__ NEWX, float* __restrict__ outAuto)
{
    int i = blockIdx.x * blockDim.x + threadIdx.x;
    if (i >= 786432) return;
    float xv = x[i], av = AUTO[i];
    NEWX[i] = xv;
    NEWX[786432 + i] = xv - av;
    outAuto[i] = av;
}

__global__ void permute_lstm_in(const float* __restrict__ OUT1, float* __restrict__ LSTMIN)
{
    int f = blockIdx.x * blockDim.x + threadIdx.x;
    if (f >= 786432) return;
    int s  = f >> 15;
    int b2 = (f >> 8) & 127;
    int g  = f & 255;
    LSTMIN[f] = OUT1[(size_t)b2 * 6144 + s * 256 + g];
}

__global__ void comb_bias(const float* __restrict__ bih0, const float* __restrict__ bhh0,
                          const float* __restrict__ bih1, const float* __restrict__ bhh1,
                          float* __restrict__ B0, float* __restrict__ B1)
{
    int i = blockIdx.x * blockDim.x + threadIdx.x;
    if (i >= 2048) return;
    B0[i] = bih0[i] + bhh0[i];
    B1[i] = bih1[i] + bhh1[i];
}

__global__ void pred_fc(const float* __restrict__ HSEQ1, const float* __restrict__ lfcW,
                        const float* __restrict__ lfcb, float* __restrict__ NF)
{
    __shared__ float hrow[512];
    int b = blockIdx.x / 12;
    int p = blockIdx.x % 12;
    int row = b * 24 + 12 + p;
    int tid = threadIdx.x;
    *(float4*)(&hrow[tid * 4]) = *(const float4*)(HSEQ1 + (size_t)row * 512 + tid * 4);
    __syncthreads();
    float acc = lfcb[tid];
    const float* wr = lfcW + (size_t)tid * 512;
#pragma unroll 8
    for (int k = 0; k < 512; k++) acc += hrow[k] * wr[k];
    NF[(size_t)b * 2560 + p * 128 + tid] = acc;
}

__global__ void concat_hidden(const float* __restrict__ HID, float* __restrict__ NF)
{
    int i = blockIdx.x * blockDim.x + threadIdx.x;
    if (i >= 65536) return;
    int b = i >> 10, j = i & 1023;
    NF[(size_t)b * 2560 + 1536 + j] = HID[i];
}

extern "C" void kernel_launch(void* const* d_in, const int* in_sizes, int n_in,
                              void* d_out, int out_size)
{
    (void)in_sizes; (void)n_in; (void)out_size;
    const float* x     = (const float*)d_in[0];
    const float* adj   = (const float*)d_in[1];
    const float* h0    = (const float*)d_in[2];
    const float* c0    = (const float*)d_in[3];
    const float* fc11W = (const float*)d_in[4];
    const float* fc11b = (const float*)d_in[5];
    const float* fc12W = (const float*)d_in[6];
    const float* fc12b = (const float*)d_in[7];
    const float* fc21W = (const float*)d_in[8];
    const float* fc21b = (const float*)d_in[9];
    const float* fc22W = (const float*)d_in[10];
    const float* fc22b = (const float*)d_in[11];
    const float* gc1W  = (const float*)d_in[12];
    const float* gc1b  = (const float*)d_in[13];
    const float* gc2W  = (const float*)d_in[14];
    const float* gc2b  = (const float*)d_in[15];
    const float* Wih0  = (const float*)d_in[16];
    const float* Whh0  = (const float*)d_in[17];
    const float* bih0  = (const float*)d_in[18];
    const float* bhh0  = (const float*)d_in[19];
    const float* Wih1  = (const float*)d_in[20];
    const float* Whh1  = (const float*)d_in[21];
    const float* bih1  = (const float*)d_in[22];
    const float* bhh1  = (const float*)d_in[23];
    const float* lfcW  = (const float*)d_in[24];
    const float* lfcb  = (const float*)d_in[25];
    const float* fcW   = (const float*)d_in[26];
    const float* fcb   = (const float*)d_in[27];

    float* out = (float*)d_out;
    float* outAuto = out + 393216;

    float* Sc;
    cudaGetSymbolAddress((void**)&Sc, g_scratch);
    float* T1     = Sc + OFF_T1;
    float* HID    = Sc + OFF_HID;
    float* T2     = Sc + OFF_T2;
    float* AUTO   = Sc + OFF_AUTO;
    float* NEWX   = Sc + OFF_NEWX;
    float* M1     = Sc + OFF_M1;
    float* H1     = Sc + OFF_H1;
    float* M2     = Sc + OFF_M2;
    float* OUT1   = Sc + OFF_OUT1;
    float* LSTMIN = Sc + OFF_LSTMIN;
    float* XG     = Sc + OFF_XG;
    float* HSEQ0  = Sc + OFF_HSEQ0;
    float* HSEQ1  = Sc + OFF_HSEQ1;
    float* HA     = Sc + OFF_HA;
    float* HB     = Sc + OFF_HB;
    float* NF     = Sc + OFF_NF;
    float* B0     = Sc + OFF_B0;
    float* B1     = Sc + OFF_B1;
    float* GP     = Sc + OFF_GP;
    __nv_bfloat16* W0HI = (__nv_bfloat16*)(Sc + OFF_W0HI);
    __nv_bfloat16* W0LO = (__nv_bfloat16*)(Sc + OFF_W0LO);
    __nv_bfloat16* W1HI = (__nv_bfloat16*)(Sc + OFF_W1HI);
    __nv_bfloat16* W1LO = (__nv_bfloat16*)(Sc + OFF_W1LO);

    static bool attr_set = false;
    if (!attr_set) {
        cudaFuncSetAttribute(fused_lstm, cudaFuncAttributeMaxDynamicSharedMemorySize,
                             SM_TOTAL_LSTM);
        attr_set = true;
    }

    split_w<<<4096, 256>>>(Whh0, W0HI, W0LO, 2048 * 512);
    split_w<<<4096, 256>>>(Whh1, W1HI, W1LO, 2048 * 512);
    comb_bias<<<8, 256>>>(bih0, bhh0, bih1, bhh1, B0, B1);

    gemm_bf3<<<dim3(32, 1, 12), 256>>>(x, fc11W, nullptr, GP, 64, 4096, 12288, 12, 0);
    reduce_bias_act<<<1024, 256>>>(GP, fc11b, T1, 262144, 4096, 12, 1);
    gemm_bf3<<<dim3(8, 1, 32), 256>>>(T1, fc12W, nullptr, GP, 64, 1024, 4096, 32, 0);
    reduce_bias_act<<<256, 256>>>(GP, fc12b, HID, 65536, 1024, 32, 1);
    gemm_bf3<<<dim3(32, 1, 8), 256>>>(HID, fc21W, nullptr, GP, 64, 4096, 1024, 8, 0);
    reduce_bias_act<<<1024, 256>>>(GP, fc21b, T2, 262144, 4096, 8, 1);
    gemm_bf3<<<dim3(96, 1, 4), 256>>>(T2, fc22W, nullptr, GP, 64, 12288, 4096, 4, 0);
    reduce_bias_act<<<3072, 256>>>(GP, fc22b, AUTO, 786432, 12288, 4, 1);
    ae_post<<<3072, 256>>>(x, AUTO, NEWX, outAuto);

    gemm_bf3<<<dim3(4, 48, 1), 256>>>(NEWX, adj, nullptr, M1, 3072, 512, 512, 1, 0);
    gemm_bf3<<<dim3(4, 48, 1), 256>>>(M1, gc1W, gc1b, H1, 3072, 512, 512, 1, 1);
    gemm_bf3<<<dim3(4, 48, 1), 256>>>(H1, adj, nullptr, M2, 3072, 512, 512, 1, 0);
    gemm_bf3<<<dim3(2, 48, 1), 256>>>(M2, gc2W, gc2b, OUT1, 3072, 256, 512, 1, 0);
    permute_lstm_in<<<3072, 256>>>(OUT1, LSTMIN);

    gemm_bf3<<<dim3(16, 24, 1), 256>>>(LSTMIN, Wih0, B0, XG, 1536, 2048, 512, 1, 0);
    fused_lstm<<<LSTM_NBLK, 256, SM_TOTAL_LSTM>>>(W0HI, W0LO, XG, h0, c0, HSEQ0, HA, HB);
    gemm_bf3<<<dim3(16, 24, 1), 256>>>(HSEQ0, Wih1, B1, XG, 1536, 2048, 512, 1, 0);
    fused_lstm<<<LSTM_NBLK, 256, SM_TOTAL_LSTM>>>(W1HI, W1LO, XG, h0 + 32768, c0 + 32768,
                                                  HSEQ1, HA, HB);

    pred_fc<<<768, 128>>>(HSEQ1, lfcW, lfcb, NF);
    concat_hidden<<<256, 256>>>(HID, NF);
    gemm_bf3<<<dim3(48, 1, 8), 256>>>(NF, fcW, nullptr, GP, 64, 6144, 2560, 8, 0);
    reduce_bias_act<<<1536, 256>>>(GP, fcb, out, 393216, 6144, 8, 0);
}